// round 15
// baseline (speedup 1.0000x reference)
#include <cuda_runtime.h>
#include <cuda_bf16.h>
#include <cstdint>

// ---------------------------------------------------------------------------
// ArcFace loss on GB300 (sm_103a). mma.sync bf16 pipeline (tcgen05 rejected by
// the harness's compute_103 target; fp8 mma.sync measured SLOWER than bf16).
//   k_prep  : W rows L2-normalized fp32 -> bf16 (g_wn); X rows likewise.
//   k_main  : PERSISTENT grid (296 CTAs = 2/SM), dynamic tile queue over
//             3128 tiles (4 M-tiles x 782 chunks of 128 classes). Per tile:
//             3-slot cp.async XW pipeline, 64x32 warp tiles, ldmatrix.x4 +
//             HMMA, cos == acc (W pre-normalized), fused exp(64*cos-64) row
//             sums (fixed-max LSE trick).
//   k_final : per-row combine of 782 partials + margin + nll; last block
//             (counter) reduces 512 nll values to the mean and resets queues.
// ---------------------------------------------------------------------------

namespace {
constexpr int NUM_C = 100000;
constexpr int DIM   = 512;
constexpr int NB    = 512;

constexpr int NPC   = 128;                        // classes per chunk
constexpr int NCCH  = (NUM_C + NPC - 1) / NPC;    // 782
constexpr int NCHP  = 784;                        // padded partial stride
constexpr int CPAD  = NCCH * NPC;                 // 100096
constexpr int NTILE = 4 * NCCH;                   // 3128

constexpr int GRID  = 296;               // 2 CTAs/SM, fully resident

constexpr int SM_X  = 0;                 // 3 stages * 16384 = 49152
constexpr int SM_W  = 49152;             // 3 stages * 16384 = 49152
constexpr size_t SMEM_BYTES = 98304;     // 2 CTAs/SM -> 192KB

constexpr float COS_M = 0.8775825618903728f;   // cos(0.5)
constexpr float SIN_M = 0.479425538604203f;    // sin(0.5)
constexpr float THv   = -0.8775825618903728f;  // -cos(m)
constexpr float MMRG  = 0.2397127693021015f;   // sin(m)*m
} // namespace

__device__ __align__(16) __nv_bfloat16 g_xn[NB * DIM];
__device__ __align__(16) __nv_bfloat16 g_wn[(size_t)CPAD * DIM];
__device__ float g_tgt[NB];
__device__ float g_partial[(size_t)NB * NCHP];   // [row][chunk]
__device__ float g_nll[NB];
__device__ unsigned g_cnt = 0;
__device__ int g_tq = 0;                         // persistent tile queue

// ---------------------------------------------------------------------------
__device__ __forceinline__ uint32_t smem_u32(const void* p) {
    uint32_t a;
    asm("{ .reg .u64 t; cvta.to.shared.u64 t, %1; cvt.u32.u64 %0, t; }"
        : "=r"(a) : "l"(p));
    return a;
}
#define CP_ASYNC16(dst, src) \
    asm volatile("cp.async.cg.shared.global [%0], [%1], 16;" \
                 :: "r"(dst), "l"(src) : "memory")
#define CP_COMMIT() asm volatile("cp.async.commit_group;" ::: "memory")
#define CP_WAIT1()  asm volatile("cp.async.wait_group 1;" ::: "memory")

#define LDSM4(r, addr) \
    asm volatile("ldmatrix.sync.aligned.m8n8.x4.shared.b16 {%0,%1,%2,%3}, [%4];" \
                 : "=r"((r)[0]), "=r"((r)[1]), "=r"((r)[2]), "=r"((r)[3])        \
                 : "r"(addr))

__device__ __forceinline__ void mma16816(float* c, const uint32_t* a,
                                         const uint32_t* b) {
    asm volatile(
        "mma.sync.aligned.m16n8k16.row.col.f32.bf16.bf16.f32 "
        "{%0,%1,%2,%3}, {%4,%5,%6,%7}, {%8,%9}, {%0,%1,%2,%3};\n"
        : "+f"(c[0]), "+f"(c[1]), "+f"(c[2]), "+f"(c[3])
        : "r"(a[0]), "r"(a[1]), "r"(a[2]), "r"(a[3]), "r"(b[0]), "r"(b[1]));
}

__device__ __forceinline__ void norm_store(float4 v0, float4 v1, float4 v2,
                                           float4 v3, float inv,
                                           uint4* dst, int lane) {
    __nv_bfloat162 p0 = __floats2bfloat162_rn(v0.x * inv, v0.y * inv);
    __nv_bfloat162 p1 = __floats2bfloat162_rn(v0.z * inv, v0.w * inv);
    __nv_bfloat162 p2 = __floats2bfloat162_rn(v1.x * inv, v1.y * inv);
    __nv_bfloat162 p3 = __floats2bfloat162_rn(v1.z * inv, v1.w * inv);
    uint4 u0 = { *(uint32_t*)&p0, *(uint32_t*)&p1,
                 *(uint32_t*)&p2, *(uint32_t*)&p3 };
    __nv_bfloat162 q0 = __floats2bfloat162_rn(v2.x * inv, v2.y * inv);
    __nv_bfloat162 q1 = __floats2bfloat162_rn(v2.z * inv, v2.w * inv);
    __nv_bfloat162 q2 = __floats2bfloat162_rn(v3.x * inv, v3.y * inv);
    __nv_bfloat162 q3 = __floats2bfloat162_rn(v3.z * inv, v3.w * inv);
    uint4 u1 = { *(uint32_t*)&q0, *(uint32_t*)&q1,
                 *(uint32_t*)&q2, *(uint32_t*)&q3 };
    dst[lane]      = u0;
    dst[lane + 32] = u1;
}

// ---------------------------------------------------------------------------
// Prep: blocks 0..1563 normalize 64 W rows each (zero past NUM_C);
//       blocks 1564..1565 normalize 256 X rows each. Rows in pairs for MLP.
// ---------------------------------------------------------------------------
__global__ void k_prep(const float* __restrict__ x, const float* __restrict__ w) {
    const int bid  = blockIdx.x;
    const int wid  = threadIdx.x >> 5;
    const int lane = threadIdx.x & 31;

    const bool is_w = (bid < CPAD / 64);
    const float* src_mat = is_w ? w : x;
    const int nrows      = is_w ? NUM_C : NB;
    __nv_bfloat16* dst_mat = is_w ? g_wn : g_xn;
    const int base = is_w ? (bid * 64 + wid * 8)
                          : ((bid - CPAD / 64) * 256 + wid * 32);
    const int per  = is_w ? 8 : 32;

    for (int rp = 0; rp < per; rp += 2) {
        const int r0 = base + rp, r1 = r0 + 1;
        float4 a0, a1, a2, a3, b0, b1, b2, b3;
        const bool ok0 = r0 < nrows, ok1 = r1 < nrows;
        if (ok0) {
            const float4* p = (const float4*)(src_mat + (size_t)r0 * DIM);
            a0 = p[2 * lane]; a1 = p[2 * lane + 1];
            a2 = p[2 * lane + 64]; a3 = p[2 * lane + 65];
        } else a0 = a1 = a2 = a3 = make_float4(0.f, 0.f, 0.f, 0.f);
        if (ok1) {
            const float4* p = (const float4*)(src_mat + (size_t)r1 * DIM);
            b0 = p[2 * lane]; b1 = p[2 * lane + 1];
            b2 = p[2 * lane + 64]; b3 = p[2 * lane + 65];
        } else b0 = b1 = b2 = b3 = make_float4(0.f, 0.f, 0.f, 0.f);

        float s0 = a0.x * a0.x + a0.y * a0.y + a0.z * a0.z + a0.w * a0.w
                 + a1.x * a1.x + a1.y * a1.y + a1.z * a1.z + a1.w * a1.w
                 + a2.x * a2.x + a2.y * a2.y + a2.z * a2.z + a2.w * a2.w
                 + a3.x * a3.x + a3.y * a3.y + a3.z * a3.z + a3.w * a3.w;
        float s1 = b0.x * b0.x + b0.y * b0.y + b0.z * b0.z + b0.w * b0.w
                 + b1.x * b1.x + b1.y * b1.y + b1.z * b1.z + b1.w * b1.w
                 + b2.x * b2.x + b2.y * b2.y + b2.z * b2.z + b2.w * b2.w
                 + b3.x * b3.x + b3.y * b3.y + b3.z * b3.z + b3.w * b3.w;
        #pragma unroll
        for (int o = 16; o; o >>= 1) {
            s0 += __shfl_xor_sync(0xFFFFFFFFu, s0, o);
            s1 += __shfl_xor_sync(0xFFFFFFFFu, s1, o);
        }
        const float inv0 = ok0 ? rsqrtf(fmaxf(s0, 1e-24f)) : 0.f;
        const float inv1 = ok1 ? rsqrtf(fmaxf(s1, 1e-24f)) : 0.f;
        norm_store(a0, a1, a2, a3, inv0,
                   (uint4*)(dst_mat + (size_t)r0 * DIM), lane);
        if (is_w || ok1)
            norm_store(b0, b1, b2, b3, inv1,
                       (uint4*)(dst_mat + (size_t)r1 * DIM), lane);
    }
}

// ---------------------------------------------------------------------------
__global__ void __launch_bounds__(256, 2)
k_main(const int* __restrict__ y) {
    extern __shared__ char smem[];
    __shared__ int s_t;
    const uint32_t sb = smem_u32(smem);
    const int tid  = threadIdx.x;
    const int wid  = tid >> 5;
    const int lane = tid & 31;
    const int wm   = wid >> 2;             // 0..1  (64-row half)
    const int wn   = wid & 3;              // 0..3  (32-col slice)

    const uint32_t swz      = (lane & 7) << 4;
    const uint32_t xrowbase = (wm * 64 + (lane & 15)) * 128;
    const uint32_t kxA      = (lane >> 4) << 4;
    const uint32_t browbase = (wn * 32 + (lane & 7) + ((lane >> 4) << 3)) * 128;
    const uint32_t kxB      = ((lane >> 3) & 1) << 4;

    for (;;) {
        // claim next tile (one ATOMG per ~23K-cycle tile; also serves as the
        // barrier protecting racc reuse from the previous tile's epilogue)
        if (tid == 0) s_t = atomicAdd(&g_tq, 1);
        __syncthreads();
        const int t = s_t;
        if (t >= NTILE) break;
        const int cc = t >> 2;
        const int mt = t & 3;
        const int c0 = cc * NPC;

        const char* xsrc = (const char*)g_xn + (size_t)mt * 128 * DIM * 2;
        const char* wsrc = (const char*)g_wn + (size_t)c0 * DIM * 2;

        #define ISSUE_XW(kc) do {                                             \
            uint32_t xs_ = sb + SM_X + ((kc) % 3) * 16384;                    \
            uint32_t ws_ = sb + SM_W + ((kc) % 3) * 16384;                    \
            _Pragma("unroll")                                                 \
            for (int i = 0; i < 4; ++i) {                                     \
                int li = tid + 256 * i;                                       \
                int row = li >> 3, seg = li & 7;                              \
                uint32_t off = row * 128 + ((seg * 16) ^ ((row & 7) << 4));   \
                size_t goff = ((size_t)row * DIM + (kc) * 64 + seg * 8) * 2;  \
                CP_ASYNC16(xs_ + off, xsrc + goff);                           \
                CP_ASYNC16(ws_ + off, wsrc + goff);                           \
            }                                                                 \
        } while (0)

        ISSUE_XW(0); CP_COMMIT();
        ISSUE_XW(1); CP_COMMIT();

        float acc[4][4][4];
        #pragma unroll
        for (int mi = 0; mi < 4; ++mi)
            #pragma unroll
            for (int ni = 0; ni < 4; ++ni)
                #pragma unroll
                for (int j = 0; j < 4; ++j) acc[mi][ni][j] = 0.f;

        for (int kc = 0; kc < 8; ++kc) {
            CP_WAIT1();
            __syncthreads();
            if (kc < 6) ISSUE_XW(kc + 2);
            CP_COMMIT();

            const uint32_t xch = sb + SM_X + (kc % 3) * 16384 + xrowbase;
            const uint32_t wst = sb + SM_W + (kc % 3) * 16384 + browbase;
            #pragma unroll
            for (int ks = 0; ks < 4; ++ks) {
                uint32_t a[4][4], bq[2][4];
                const uint32_t ka = (uint32_t)(ks * 32 + kxA) ^ swz;
                const uint32_t kb = (uint32_t)(ks * 32 + kxB) ^ swz;
                #pragma unroll
                for (int mi = 0; mi < 4; ++mi) LDSM4(a[mi], xch + mi * 2048 + ka);
                #pragma unroll
                for (int nb = 0; nb < 2; ++nb) LDSM4(bq[nb], wst + nb * 2048 + kb);
                #pragma unroll
                for (int mi = 0; mi < 4; ++mi)
                    #pragma unroll
                    for (int nb = 0; nb < 2; ++nb) {
                        mma16816(acc[mi][2 * nb],     a[mi], &bq[nb][0]);
                        mma16816(acc[mi][2 * nb + 1], a[mi], &bq[nb][2]);
                    }
            }
        }

        // ---- epilogue: cos == acc; rowsum exp(64*cos - 64) ----
        // racc overlays X stage 0 (last consumed at kc=6; all warps are past
        // the kc=7 top barrier). Next tile's reuse is guarded by the
        // claim-barrier at loop top.
        float* racc = (float*)(smem + SM_X);
        const int qq = lane & 3;
        const int g8 = lane >> 2;

        #pragma unroll
        for (int mi = 0; mi < 4; ++mi) {
            #pragma unroll
            for (int h = 0; h < 2; ++h) {
                const int lrow = wm * 64 + mi * 16 + g8 + 8 * h;
                const int grow = mt * 128 + lrow;
                const int yv   = y[grow];
                float rs = 0.f;
                #pragma unroll
                for (int ni = 0; ni < 4; ++ni) {
                    const int cb = c0 + wn * 32 + ni * 8 + 2 * qq;
                    float cv0 = acc[mi][ni][2 * h + 0];
                    float cv1 = acc[mi][ni][2 * h + 1];
                    if (cb == yv)     g_tgt[grow] = cv0;
                    if (cb + 1 == yv) g_tgt[grow] = cv1;
                    float e0 = __expf(fmaf(cv0, 64.f, -64.f));
                    float e1 = __expf(fmaf(cv1, 64.f, -64.f));
                    if (cb < NUM_C)     rs += e0;
                    if (cb + 1 < NUM_C) rs += e1;
                }
                rs += __shfl_xor_sync(0xFFFFFFFFu, rs, 1);
                rs += __shfl_xor_sync(0xFFFFFFFFu, rs, 2);
                if (qq == 0) racc[lrow * 4 + wn] = rs;
            }
        }
        __syncthreads();
        if (tid < 128) {
            float s = racc[tid * 4 + 0] + racc[tid * 4 + 1]
                    + racc[tid * 4 + 2] + racc[tid * 4 + 3];
            g_partial[(size_t)(mt * 128 + tid) * NCHP + cc] = s;
        }
        #undef ISSUE_XW
    }
}

// ---------------------------------------------------------------------------
__global__ void k_final(float* __restrict__ out) {
    __shared__ float red[8];
    __shared__ float sred[256];
    __shared__ int slast;
    const int row = blockIdx.x;
    const int t   = threadIdx.x;

    float s = 0.f;
    for (int c = t; c < NCCH; c += 256)
        s += g_partial[(size_t)row * NCHP + c];
    #pragma unroll
    for (int o = 16; o; o >>= 1) s += __shfl_xor_sync(0xFFFFFFFFu, s, o);
    if ((t & 31) == 0) red[t >> 5] = s;
    __syncthreads();
    if (t == 0) {
        float S = 0.f;
        #pragma unroll
        for (int k = 0; k < 8; ++k) S += red[k];
        float ct  = g_tgt[row];
        float sn  = sqrtf(fmaxf(1.f - ct * ct, 0.f));
        float cwm = ct * COS_M - sn * SIN_M;
        float phi = (ct > THv) ? cwm : (ct - MMRG);
        float Sp  = S - __expf(fmaf(ct, 64.f, -64.f)) + __expf(fmaf(phi, 64.f, -64.f));
        g_nll[row] = 64.f + logf(Sp) - 64.f * phi;
        __threadfence();
        unsigned v = atomicAdd(&g_cnt, 1u);
        slast = (v == (unsigned)(gridDim.x - 1));
    }
    __syncthreads();
    if (slast) {
        __threadfence();
        float v = g_nll[t] + g_nll[t + 256];
        sred[t] = v;
        __syncthreads();
        #pragma unroll
        for (int st = 128; st; st >>= 1) {
            if (t < st) sred[t] += sred[t + st];
            __syncthreads();
        }
        if (t == 0) { out[0] = sred[0] / (float)NB; g_cnt = 0; g_tq = 0; }
    }
}

// ---------------------------------------------------------------------------
extern "C" void kernel_launch(void* const* d_in, const int* in_sizes, int n_in,
                              void* d_out, int out_size) {
    const float* x = (const float*)d_in[0];
    const int*   y = (const int*)d_in[1];
    const float* w = (const float*)d_in[2];
    float* out = (float*)d_out;

    cudaFuncSetAttribute(k_main, cudaFuncAttributeMaxDynamicSharedMemorySize,
                         (int)SMEM_BYTES);

    k_prep<<<CPAD / 64 + 2, 256>>>(x, w);
    k_main<<<GRID, 256, SMEM_BYTES>>>(y);
    k_final<<<NB, 256>>>(out);
}

// round 16
// speedup vs baseline: 1.2451x; 1.2451x over previous
#include <cuda_runtime.h>
#include <cuda_bf16.h>
#include <cstdint>

// ---------------------------------------------------------------------------
// ArcFace loss on GB300 (sm_103a). mma.sync bf16 pipeline (tcgen05 rejected by
// the harness's compute_103 target; fp8 mma.sync measured slower than bf16;
// persistent/queue/fork-join scheduling all measured slower than static).
//   k_prep  : W rows L2-normalized fp32 -> bf16 (g_wn); X rows likewise.
//             4-row batches: 16 LDG.128 in flight, 4 interleaved reductions.
//   k_main  : 3128 CTAs (4 M-tiles x 782 chunks of 128 classes), 256 thr,
//             2 CTAs/SM; 3-slot cp.async XW pipeline, 64x32 warp tiles,
//             ldmatrix.x4 + HMMA; cos == acc; fused exp(64*cos-64) row sums
//             (fixed-max LSE trick); rows accumulated via atomicAdd.
//   k_final : single block: margin + nll per row + mean; resets g_rowsum.
// ---------------------------------------------------------------------------

namespace {
constexpr int NUM_C = 100000;
constexpr int DIM   = 512;
constexpr int NB    = 512;

constexpr int NPC   = 128;                        // classes per chunk
constexpr int NCCH  = (NUM_C + NPC - 1) / NPC;    // 782
constexpr int CPAD  = NCCH * NPC;                 // 100096

constexpr int SM_X  = 0;                 // 3 stages * 16384 = 49152
constexpr int SM_W  = 49152;             // 3 stages * 16384 = 49152
constexpr size_t SMEM_BYTES = 98304;     // 2 CTAs/SM

constexpr float COS_M = 0.8775825618903728f;   // cos(0.5)
constexpr float SIN_M = 0.479425538604203f;    // sin(0.5)
constexpr float THv   = -0.8775825618903728f;  // -cos(m)
constexpr float MMRG  = 0.2397127693021015f;   // sin(m)*m
} // namespace

__device__ __align__(16) __nv_bfloat16 g_xn[NB * DIM];
__device__ __align__(16) __nv_bfloat16 g_wn[(size_t)CPAD * DIM];
__device__ float g_tgt[NB];
__device__ float g_rowsum[NB];        // atomically accumulated exp-sums
                                      // (zero-init; k_final resets per replay)

// ---------------------------------------------------------------------------
__device__ __forceinline__ uint32_t smem_u32(const void* p) {
    uint32_t a;
    asm("{ .reg .u64 t; cvta.to.shared.u64 t, %1; cvt.u32.u64 %0, t; }"
        : "=r"(a) : "l"(p));
    return a;
}
#define CP_ASYNC16(dst, src) \
    asm volatile("cp.async.cg.shared.global [%0], [%1], 16;" \
                 :: "r"(dst), "l"(src) : "memory")
#define CP_COMMIT() asm volatile("cp.async.commit_group;" ::: "memory")
#define CP_WAIT1()  asm volatile("cp.async.wait_group 1;" ::: "memory")

#define LDSM4(r, addr) \
    asm volatile("ldmatrix.sync.aligned.m8n8.x4.shared.b16 {%0,%1,%2,%3}, [%4];" \
                 : "=r"((r)[0]), "=r"((r)[1]), "=r"((r)[2]), "=r"((r)[3])        \
                 : "r"(addr))

__device__ __forceinline__ void mma16816(float* c, const uint32_t* a,
                                         const uint32_t* b) {
    asm volatile(
        "mma.sync.aligned.m16n8k16.row.col.f32.bf16.bf16.f32 "
        "{%0,%1,%2,%3}, {%4,%5,%6,%7}, {%8,%9}, {%0,%1,%2,%3};\n"
        : "+f"(c[0]), "+f"(c[1]), "+f"(c[2]), "+f"(c[3])
        : "r"(a[0]), "r"(a[1]), "r"(a[2]), "r"(a[3]), "r"(b[0]), "r"(b[1]));
}

__device__ __forceinline__ void norm_store(float4 v0, float4 v1, float4 v2,
                                           float4 v3, float inv,
                                           uint4* dst, int lane) {
    __nv_bfloat162 p0 = __floats2bfloat162_rn(v0.x * inv, v0.y * inv);
    __nv_bfloat162 p1 = __floats2bfloat162_rn(v0.z * inv, v0.w * inv);
    __nv_bfloat162 p2 = __floats2bfloat162_rn(v1.x * inv, v1.y * inv);
    __nv_bfloat162 p3 = __floats2bfloat162_rn(v1.z * inv, v1.w * inv);
    uint4 u0 = { *(uint32_t*)&p0, *(uint32_t*)&p1,
                 *(uint32_t*)&p2, *(uint32_t*)&p3 };
    __nv_bfloat162 q0 = __floats2bfloat162_rn(v2.x * inv, v2.y * inv);
    __nv_bfloat162 q1 = __floats2bfloat162_rn(v2.z * inv, v2.w * inv);
    __nv_bfloat162 q2 = __floats2bfloat162_rn(v3.x * inv, v3.y * inv);
    __nv_bfloat162 q3 = __floats2bfloat162_rn(v3.z * inv, v3.w * inv);
    uint4 u1 = { *(uint32_t*)&q0, *(uint32_t*)&q1,
                 *(uint32_t*)&q2, *(uint32_t*)&q3 };
    dst[lane]      = u0;
    dst[lane + 32] = u1;
}

// ---------------------------------------------------------------------------
// Prep: blocks 0..1563 normalize 64 W rows each (zero past NUM_C);
//       blocks 1564..1565 normalize 256 X rows each.
//       4-row batches: 16 LDG.128 in flight, 4 interleaved reductions.
// ---------------------------------------------------------------------------
__global__ void k_prep(const float* __restrict__ x, const float* __restrict__ w) {
    const int bid  = blockIdx.x;
    const int wid  = threadIdx.x >> 5;
    const int lane = threadIdx.x & 31;

    const bool is_w = (bid < CPAD / 64);
    const float* src_mat = is_w ? w : x;
    const int nrows      = is_w ? NUM_C : NB;
    __nv_bfloat16* dst_mat = is_w ? g_wn : g_xn;
    const int base = is_w ? (bid * 64 + wid * 8)
                          : ((bid - CPAD / 64) * 256 + wid * 32);
    const int per  = is_w ? 8 : 32;

    for (int rp = 0; rp < per; rp += 4) {
        float4 v[4][4];
        float  s[4];
        bool   ok[4];
        #pragma unroll
        for (int j = 0; j < 4; ++j) {
            const int r = base + rp + j;
            ok[j] = r < nrows;
            if (ok[j]) {
                const float4* p = (const float4*)(src_mat + (size_t)r * DIM);
                v[j][0] = p[2 * lane];      v[j][1] = p[2 * lane + 1];
                v[j][2] = p[2 * lane + 64]; v[j][3] = p[2 * lane + 65];
            } else {
                v[j][0] = v[j][1] = v[j][2] = v[j][3] =
                    make_float4(0.f, 0.f, 0.f, 0.f);
            }
        }
        #pragma unroll
        for (int j = 0; j < 4; ++j)
            s[j] = v[j][0].x * v[j][0].x + v[j][0].y * v[j][0].y
                 + v[j][0].z * v[j][0].z + v[j][0].w * v[j][0].w
                 + v[j][1].x * v[j][1].x + v[j][1].y * v[j][1].y
                 + v[j][1].z * v[j][1].z + v[j][1].w * v[j][1].w
                 + v[j][2].x * v[j][2].x + v[j][2].y * v[j][2].y
                 + v[j][2].z * v[j][2].z + v[j][2].w * v[j][2].w
                 + v[j][3].x * v[j][3].x + v[j][3].y * v[j][3].y
                 + v[j][3].z * v[j][3].z + v[j][3].w * v[j][3].w;
        #pragma unroll
        for (int o = 16; o; o >>= 1) {
            #pragma unroll
            for (int j = 0; j < 4; ++j)
                s[j] += __shfl_xor_sync(0xFFFFFFFFu, s[j], o);
        }
        #pragma unroll
        for (int j = 0; j < 4; ++j) {
            const int r = base + rp + j;
            const float inv = ok[j] ? rsqrtf(fmaxf(s[j], 1e-24f)) : 0.f;
            if (is_w || ok[j])
                norm_store(v[j][0], v[j][1], v[j][2], v[j][3], inv,
                           (uint4*)(dst_mat + (size_t)r * DIM), lane);
        }
    }
}

// ---------------------------------------------------------------------------
__global__ void __launch_bounds__(256, 2)
k_main(const int* __restrict__ y) {
    extern __shared__ char smem[];
    const uint32_t sb = smem_u32(smem);
    const int tid  = threadIdx.x;
    const int wid  = tid >> 5;
    const int lane = tid & 31;
    const int mt   = blockIdx.x;           // 0..3 (128-row tile)
    const int cch  = blockIdx.y;           // 0..781
    const int c0   = cch * NPC;
    const int wm   = wid >> 2;             // 0..1  (64-row half)
    const int wn   = wid & 3;              // 0..3  (32-col slice)

    const char* xsrc = (const char*)g_xn + (size_t)mt * 128 * DIM * 2;
    const char* wsrc = (const char*)g_wn + (size_t)c0 * DIM * 2;

    #define ISSUE_XW(kc) do {                                                 \
        uint32_t xs_ = sb + SM_X + ((kc) % 3) * 16384;                        \
        uint32_t ws_ = sb + SM_W + ((kc) % 3) * 16384;                        \
        _Pragma("unroll")                                                     \
        for (int i = 0; i < 4; ++i) {                                         \
            int li = tid + 256 * i;                                           \
            int row = li >> 3, seg = li & 7;                                  \
            uint32_t off = row * 128 + ((seg * 16) ^ ((row & 7) << 4));       \
            size_t goff = ((size_t)row * DIM + (kc) * 64 + seg * 8) * 2;      \
            CP_ASYNC16(xs_ + off, xsrc + goff);                               \
            CP_ASYNC16(ws_ + off, wsrc + goff);                               \
        }                                                                     \
    } while (0)

    ISSUE_XW(0); CP_COMMIT();
    ISSUE_XW(1); CP_COMMIT();

    float acc[4][4][4];
    #pragma unroll
    for (int mi = 0; mi < 4; ++mi)
        #pragma unroll
        for (int ni = 0; ni < 4; ++ni)
            #pragma unroll
            for (int j = 0; j < 4; ++j) acc[mi][ni][j] = 0.f;

    const uint32_t swz      = (lane & 7) << 4;
    const uint32_t xrowbase = (wm * 64 + (lane & 15)) * 128;
    const uint32_t kxA      = (lane >> 4) << 4;
    const uint32_t browbase = (wn * 32 + (lane & 7) + ((lane >> 4) << 3)) * 128;
    const uint32_t kxB      = ((lane >> 3) & 1) << 4;

    for (int kc = 0; kc < 8; ++kc) {
        CP_WAIT1();
        __syncthreads();
        if (kc < 6) ISSUE_XW(kc + 2);
        CP_COMMIT();

        const uint32_t xch = sb + SM_X + (kc % 3) * 16384 + xrowbase;
        const uint32_t wst = sb + SM_W + (kc % 3) * 16384 + browbase;
        #pragma unroll
        for (int ks = 0; ks < 4; ++ks) {
            uint32_t a[4][4], bq[2][4];
            const uint32_t ka = (uint32_t)(ks * 32 + kxA) ^ swz;
            const uint32_t kb = (uint32_t)(ks * 32 + kxB) ^ swz;
            #pragma unroll
            for (int mi = 0; mi < 4; ++mi) LDSM4(a[mi], xch + mi * 2048 + ka);
            #pragma unroll
            for (int nb = 0; nb < 2; ++nb) LDSM4(bq[nb], wst + nb * 2048 + kb);
            #pragma unroll
            for (int mi = 0; mi < 4; ++mi)
                #pragma unroll
                for (int nb = 0; nb < 2; ++nb) {
                    mma16816(acc[mi][2 * nb],     a[mi], &bq[nb][0]);
                    mma16816(acc[mi][2 * nb + 1], a[mi], &bq[nb][2]);
                }
        }
    }

    // ---- epilogue: cos == acc (W pre-normalized); rowsum exp(64*cos-64) ---
    float* racc = (float*)(smem + SM_X);
    const int qq = lane & 3;
    const int g8 = lane >> 2;

    #pragma unroll
    for (int mi = 0; mi < 4; ++mi) {
        #pragma unroll
        for (int h = 0; h < 2; ++h) {
            const int lrow = wm * 64 + mi * 16 + g8 + 8 * h;
            const int grow = mt * 128 + lrow;
            const int yv   = y[grow];
            float rs = 0.f;
            #pragma unroll
            for (int ni = 0; ni < 4; ++ni) {
                const int cb = c0 + wn * 32 + ni * 8 + 2 * qq;
                float cv0 = acc[mi][ni][2 * h + 0];
                float cv1 = acc[mi][ni][2 * h + 1];
                if (cb == yv)     g_tgt[grow] = cv0;
                if (cb + 1 == yv) g_tgt[grow] = cv1;
                float e0 = __expf(fmaf(cv0, 64.f, -64.f));
                float e1 = __expf(fmaf(cv1, 64.f, -64.f));
                if (cb < NUM_C)     rs += e0;
                if (cb + 1 < NUM_C) rs += e1;
            }
            rs += __shfl_xor_sync(0xFFFFFFFFu, rs, 1);
            rs += __shfl_xor_sync(0xFFFFFFFFu, rs, 2);
            if (qq == 0) racc[lrow * 4 + wn] = rs;
        }
    }
    __syncthreads();
    if (tid < 128) {
        float s = racc[tid * 4 + 0] + racc[tid * 4 + 1]
                + racc[tid * 4 + 2] + racc[tid * 4 + 3];
        atomicAdd(&g_rowsum[mt * 128 + tid], s);
    }
    #undef ISSUE_XW
}

// ---------------------------------------------------------------------------
// k_final: one 512-thread block. Margin + nll per row, mean, and reset of
// g_rowsum for the next graph replay.
__global__ void k_final(float* __restrict__ out) {
    __shared__ float red[NB];
    const int t = threadIdx.x;

    float S = g_rowsum[t];
    g_rowsum[t] = 0.f;                 // reset for next replay

    float ct  = g_tgt[t];
    float sn  = sqrtf(fmaxf(1.f - ct * ct, 0.f));
    float cwm = ct * COS_M - sn * SIN_M;
    float phi = (ct > THv) ? cwm : (ct - MMRG);
    float Sp  = S - __expf(fmaf(ct, 64.f, -64.f)) + __expf(fmaf(phi, 64.f, -64.f));
    red[t] = 64.f + logf(Sp) - 64.f * phi;
    __syncthreads();
    #pragma unroll
    for (int st = 256; st; st >>= 1) {
        if (t < st) red[t] += red[t + st];
        __syncthreads();
    }
    if (t == 0) out[0] = red[0] / (float)NB;
}

// ---------------------------------------------------------------------------
extern "C" void kernel_launch(void* const* d_in, const int* in_sizes, int n_in,
                              void* d_out, int out_size) {
    const float* x = (const float*)d_in[0];
    const int*   y = (const int*)d_in[1];
    const float* w = (const float*)d_in[2];
    float* out = (float*)d_out;

    cudaFuncSetAttribute(k_main, cudaFuncAttributeMaxDynamicSharedMemorySize,
                         (int)SMEM_BYTES);

    k_prep<<<CPAD / 64 + 2, 256>>>(x, w);
    k_main<<<dim3(4, NCCH), 256, SMEM_BYTES>>>(y);
    k_final<<<1, NB>>>(out);
}